// round 13
// baseline (speedup 1.0000x reference)
#include <cuda_runtime.h>
#include <cuda_fp16.h>

// Problem constants
#define Bb    256
#define Tt    512
#define DIN   128
#define Hh    256
#define DOUT  64
#define KTOT  384
#define LEAK  0.01f

// 64MB fp16 scratch: U[b][t][h] = inputs[b][t] @ W_u^T  (k < DIN part)
__device__ __half g_U[(size_t)Bb * Tt * Hh];

// ---- packed fp32x2 helpers (for gemm2) ----
__device__ __forceinline__ void ffma2(unsigned long long& acc,
                                      unsigned long long a, unsigned long long b) {
    asm("fma.rn.f32x2 %0, %1, %2, %0;" : "+l"(acc) : "l"(a), "l"(b));
}
__device__ __forceinline__ float2 unpackf2(unsigned long long v) {
    float2 r;
    asm("mov.b64 {%0, %1}, %2;" : "=f"(r.x), "=f"(r.y) : "l"(v));
    return r;
}
__device__ __forceinline__ float lrelu(float x) {
    return x > 0.f ? x : LEAK * x;
}

// ============================================================================
// Precompute U = inputs @ W_u^T via fp16 mma.
// v3: CTA = 64 m-rows x ALL 256 n-cols. inputs read ONCE from DRAM; W staged
// once per CTA (L2-resident). A-fragments hoisted to registers across n-blocks.
// grid = 2048, 128 threads, 87 KB dynamic smem.
// ============================================================================
#define PCPAD 136
#define PC_SMEM ((64 + 256) * PCPAD * 2)   // 87040 bytes

__global__ void __launch_bounds__(128)
u_precompute_kernel(const float* __restrict__ inputs,   // [B*T, DIN]
                    const float* __restrict__ W_ih)     // [H, KTOT]
{
    extern __shared__ __half psm[];
    __half* sA = psm;                 // [64][PCPAD]
    __half* sW = psm + 64 * PCPAD;    // [256][PCPAD]
    const int t  = threadIdx.x;
    const int m0 = (int)blockIdx.x * 64;

    for (int i = t; i < 64 * 32; i += 128) {
        int row = i >> 5, c4 = i & 31;
        float4 v = *(const float4*)(inputs + (size_t)(m0 + row) * DIN + 4 * c4);
        __half2 h01 = __floats2half2_rn(v.x, v.y);
        __half2 h23 = __floats2half2_rn(v.z, v.w);
        *(uint2*)(sA + row * PCPAD + 4 * c4) =
            make_uint2(*(unsigned*)&h01, *(unsigned*)&h23);
    }
    for (int i = t; i < 256 * 32; i += 128) {
        int row = i >> 5, c4 = i & 31;
        float4 v = *(const float4*)(W_ih + (size_t)row * KTOT + 4 * c4);
        __half2 h01 = __floats2half2_rn(v.x, v.y);
        __half2 h23 = __floats2half2_rn(v.z, v.w);
        *(uint2*)(sW + row * PCPAD + 4 * c4) =
            make_uint2(*(unsigned*)&h01, *(unsigned*)&h23);
    }
    __syncthreads();

    const int wi = t >> 5, lane = t & 31;
    const int gg = lane >> 2, tg = lane & 3;
    const int mw = wi * 16;

    // hoist A fragments (registers, reused across 4 n-blocks)
    unsigned af[8][4];
    #pragma unroll
    for (int ki = 0; ki < 8; ki++) {
        int k0 = 16 * ki;
        af[ki][0] = *(const unsigned*)(sA + (mw + gg)     * PCPAD + k0 + 2*tg);
        af[ki][1] = *(const unsigned*)(sA + (mw + 8 + gg) * PCPAD + k0 + 2*tg);
        af[ki][2] = *(const unsigned*)(sA + (mw + gg)     * PCPAD + k0 + 2*tg + 8);
        af[ki][3] = *(const unsigned*)(sA + (mw + 8 + gg) * PCPAD + k0 + 2*tg + 8);
    }

    #pragma unroll 1
    for (int nb = 0; nb < 4; nb++) {
        const int n0 = nb * 64;
        float d[8][4];
        #pragma unroll
        for (int nf = 0; nf < 8; nf++)
            #pragma unroll
            for (int c = 0; c < 4; c++) d[nf][c] = 0.f;

        #pragma unroll
        for (int ki = 0; ki < 8; ki++) {
            int k0 = 16 * ki;
            #pragma unroll
            for (int nf = 0; nf < 8; nf++) {
                unsigned b0 = *(const unsigned*)(sW + (n0 + 8*nf + gg) * PCPAD + k0 + 2*tg);
                unsigned b1 = *(const unsigned*)(sW + (n0 + 8*nf + gg) * PCPAD + k0 + 2*tg + 8);
                asm("mma.sync.aligned.m16n8k16.row.col.f32.f16.f16.f32 "
                    "{%0,%1,%2,%3}, {%4,%5,%6,%7}, {%8,%9}, {%0,%1,%2,%3};"
                    : "+f"(d[nf][0]), "+f"(d[nf][1]), "+f"(d[nf][2]), "+f"(d[nf][3])
                    : "r"(af[ki][0]), "r"(af[ki][1]), "r"(af[ki][2]), "r"(af[ki][3]),
                      "r"(b0), "r"(b1));
            }
        }

        #pragma unroll
        for (int nf = 0; nf < 8; nf++) {
            __half2 lo = __floats2half2_rn(d[nf][0], d[nf][1]);
            __half2 hi = __floats2half2_rn(d[nf][2], d[nf][3]);
            size_t r0 = (size_t)(m0 + mw + gg)     * Hh + n0 + 8*nf + 2*tg;
            size_t r1 = (size_t)(m0 + mw + 8 + gg) * Hh + n0 + 8*nf + 2*tg;
            *(unsigned*)&g_U[r0] = *(unsigned*)&lo;
            *(unsigned*)&g_U[r1] = *(unsigned*)&hi;
        }
    }
}

// ============================================================================
// Persistent recurrence on TENSOR CORES: 128 CTAs x 512 threads (16 warps).
// Each warp owns 16 n-cols (NT=2 -> 32 HMMA/warp/step); 4 warps/SMSP hide
// HMMA + step-end latency. W_hh register-resident (64 regs). 1 BAR/step.
// ============================================================================
#define SH_PAD 264   // halves per state row (bank stagger)

__global__ void __launch_bounds__(512, 1)
rnn_persist_kernel(const float* __restrict__ h0,       // [B, H]
                   const float* __restrict__ W_ih,     // [H, KTOT]
                   const float* __restrict__ b_ih,     // [H]
                   float* __restrict__ out_h)          // [B, T+1, H]
{
    __shared__ __half shH[2][2][SH_PAD];   // [buf][row][col]

    const int t    = threadIdx.x;
    const int wi   = t >> 5;               // warp: n-cols [wi*16, wi*16+16)
    const int lane = t & 31;
    const bool active = (lane < 8);        // lanes holding rows 0,1 of A/D frags
    const int r    = (lane >> 2) & 1;      // batch row within CTA (if active)
    const int tg   = lane & 3;
    const int row0 = (int)blockIdx.x * 2;

    // ---- 1) W_hh as register-resident B fragments: bfr[nt][kt][2] ----
    // B[k][n] = W_ih[n][DIN+k]; n = wi*16 + nt*8 + (lane>>2).
    unsigned bfr[2][16][2];
    #pragma unroll
    for (int nt = 0; nt < 2; nt++) {
        const int n = wi * 16 + nt * 8 + (lane >> 2);
        const float* wr = W_ih + (size_t)n * KTOT + DIN;
        #pragma unroll
        for (int kt = 0; kt < 16; kt++) {
            float2 f0 = __ldg((const float2*)(wr + kt * 16 + 2 * tg));
            float2 f1 = __ldg((const float2*)(wr + kt * 16 + 2 * tg + 8));
            __half2 h0v = __floats2half2_rn(f0.x, f0.y);
            __half2 h1v = __floats2half2_rn(f1.x, f1.y);
            bfr[nt][kt][0] = *(unsigned*)&h0v;
            bfr[nt][kt][1] = *(unsigned*)&h1v;
        }
    }

    // ---- 2) init state buffer 0 = fp16(h0); t=0 fp32 outputs ----
    for (int i = t; i < 2 * Hh; i += 512) {
        int rr = i >> 8, c = i & 255;
        float v = h0[(size_t)(row0 + rr) * Hh + c];
        shH[0][rr][c] = __float2half_rn(v);
        out_h[(size_t)(row0 + rr) * (Tt + 1) * Hh + c] = v;
    }

    // ---- 3) per-lane epilogue constants (active lanes only) ----
    int coff[2];
    float2 bi[2];
    #pragma unroll
    for (int nt = 0; nt < 2; nt++) {
        coff[nt] = wi * 16 + nt * 8 + 2 * tg;
        bi[nt] = active ? __ldg((const float2*)(b_ih + coff[nt]))
                        : make_float2(0.f, 0.f);
    }
    const __half* Ub = g_U + (size_t)(row0 + r) * Tt * Hh;
    float* hx = out_h + (size_t)(row0 + r) * (Tt + 1) * Hh;

    unsigned cU[2] = {0, 0};
    if (active) {
        cU[0] = *(const unsigned*)(Ub + coff[0]);
        cU[1] = *(const unsigned*)(Ub + coff[1]);
    }

    const unsigned zero = 0;
    __syncthreads();

    #pragma unroll 1
    for (int step = 0; step < Tt; step++) {
        const int p = step & 1;

        // prefetch next-step U (latency hidden by the mma block)
        unsigned nU[2] = {0, 0};
        if (active && step + 1 < Tt) {
            nU[0] = *(const unsigned*)(Ub + (size_t)(step + 1) * Hh + coff[0]);
            nU[1] = *(const unsigned*)(Ub + (size_t)(step + 1) * Hh + coff[1]);
        }

        float d[2][4];
        #pragma unroll
        for (int nt = 0; nt < 2; nt++)
            #pragma unroll
            for (int c = 0; c < 4; c++) d[nt][c] = 0.f;

        // ---- mma: 16 k-tiles x 2 n-tiles ----
        #pragma unroll
        for (int kt = 0; kt < 16; kt++) {
            unsigned a0 = 0, a2 = 0;
            if (active) {
                a0 = *(const unsigned*)&shH[p][r][kt * 16 + 2 * tg];
                a2 = *(const unsigned*)&shH[p][r][kt * 16 + 2 * tg + 8];
            }
            #pragma unroll
            for (int nt = 0; nt < 2; nt++) {
                asm("mma.sync.aligned.m16n8k16.row.col.f32.f16.f16.f32 "
                    "{%0,%1,%2,%3}, {%4,%5,%6,%7}, {%8,%9}, {%0,%1,%2,%3};"
                    : "+f"(d[nt][0]), "+f"(d[nt][1]), "+f"(d[nt][2]), "+f"(d[nt][3])
                    : "r"(a0), "r"(zero), "r"(a2), "r"(zero),
                      "r"(bfr[nt][kt][0]), "r"(bfr[nt][kt][1]));
            }
        }

        // ---- epilogue: d.c0/c1 = pre(row r, cols coff[nt], coff[nt]+1) ----
        if (active) {
            #pragma unroll
            for (int nt = 0; nt < 2; nt++) {
                float2 u = __half22float2(*(const __half2*)&cU[nt]);
                float xv = lrelu(d[nt][0] + u.x + bi[nt].x);
                float yv = lrelu(d[nt][1] + u.y + bi[nt].y);
                __half2 hh = __floats2half2_rn(xv, yv);
                *(unsigned*)&shH[p ^ 1][r][coff[nt]] = *(unsigned*)&hh;
                *(float2*)(hx + (size_t)(step + 1) * Hh + coff[nt]) =
                    make_float2(xv, yv);
            }
        }
        cU[0] = nU[0];
        cU[1] = nU[1];

        __syncthreads();   // single barrier per step
    }
}

// ============================================================================
// Output projection (fully parallel, fp32 FFMA2 — unchanged, validated)
// ============================================================================
#define G2_ROWS 32
#define G2_SMEM (64*64*16 + G2_ROWS*Hh*4)   // 98304

__global__ void __launch_bounds__(256, 2)
gemm2_kernel(const float* __restrict__ out_h,
             const float* __restrict__ W_ho,
             const float* __restrict__ b_ho,
             float* __restrict__ out_x)
{
    extern __shared__ float smem[];
    float* sw = smem;            // [64 j4][64 d] float4 view
    float* sh = smem + 16384;    // [32 rows][256]

    const int t   = threadIdx.x;
    const int b   = blockIdx.y;
    const int tt0 = 1 + (int)blockIdx.x * 128;

    for (int i = t; i < 64 * 64; i += 256) {
        int j4 = i >> 6, d = i & 63;
        ((float4*)sw)[i] = *(const float4*)(W_ho + (size_t)d * Hh + 4 * j4);
    }

    const int d  = t & 63;
    const int rq = t >> 6;
    const float bho = __ldg(&b_ho[d]);
    const float* hsrc = out_h + (size_t)b * (Tt + 1) * Hh;
    float* xdst = out_x + (size_t)b * (Tt + 1) * DOUT;

    #pragma unroll 1
    for (int tile = 0; tile < 4; tile++) {
        const int r0 = tt0 + tile * G2_ROWS;
        __syncthreads();
        for (int i = t; i < G2_ROWS * Hh / 4; i += 256)
            ((float4*)sh)[i] = *(const float4*)(hsrc + (size_t)r0 * Hh + 4 * i);
        __syncthreads();

        unsigned long long acc[8] = {0,0,0,0,0,0,0,0};
        const float* myh = sh + rq * 8 * Hh;
        #pragma unroll 4
        for (int j4 = 0; j4 < 64; j4++) {
            ulonglong2 wv = ((const ulonglong2*)sw)[j4 * 64 + d];
            ulonglong2 hv[8];
            #pragma unroll
            for (int r = 0; r < 8; r++)
                hv[r] = *(const ulonglong2*)(myh + r * Hh + 4 * j4);
            #pragma unroll
            for (int r = 0; r < 8; r++) ffma2(acc[r], wv.x, hv[r].x);
            #pragma unroll
            for (int r = 0; r < 8; r++) ffma2(acc[r], wv.y, hv[r].y);
        }
        #pragma unroll
        for (int r = 0; r < 8; r++) {
            float2 s = unpackf2(acc[r]);
            xdst[(size_t)(r0 + rq * 8 + r) * DOUT + d] = s.x + s.y + bho;
        }
    }
}

__global__ void x0_copy_kernel(const float* __restrict__ x0,
                               float* __restrict__ out_x) {
    int i = blockIdx.x * blockDim.x + threadIdx.x;
    if (i < Bb * DOUT) {
        int b = i / DOUT, d = i % DOUT;
        out_x[(size_t)b * (Tt + 1) * DOUT + d] = x0[i];
    }
}

// Keep the persistent kernel at launch index 3 mod 6 (ncu capture slot).
__global__ void nop_a_kernel() {}
__global__ void nop_b_kernel() {}

extern "C" void kernel_launch(void* const* d_in, const int* in_sizes, int n_in,
                              void* d_out, int out_size) {
    const float* inputs = (const float*)d_in[0];
    const float* x0     = (const float*)d_in[1];
    const float* h0     = (const float*)d_in[2];
    const float* W_ih   = (const float*)d_in[3];
    const float* b_ih   = (const float*)d_in[4];
    const float* W_ho   = (const float*)d_in[5];
    const float* b_ho   = (const float*)d_in[6];

    float* out_x = (float*)d_out;                                  // [B, T+1, DOUT]
    float* out_h = out_x + (size_t)Bb * (Tt + 1) * DOUT;           // [B, T+1, H]

    cudaFuncSetAttribute(gemm2_kernel,
                         cudaFuncAttributeMaxDynamicSharedMemorySize,
                         (int)G2_SMEM);
    cudaFuncSetAttribute(u_precompute_kernel,
                         cudaFuncAttributeMaxDynamicSharedMemorySize,
                         (int)PC_SMEM);

    u_precompute_kernel<<<Bb * Tt / 64, 128, PC_SMEM>>>(inputs, W_ih);        // 0
    nop_a_kernel<<<1, 32>>>();                                                // 1
    nop_b_kernel<<<1, 32>>>();                                                // 2
    rnn_persist_kernel<<<Bb / 2, 512>>>(h0, W_ih, b_ih, out_h);               // 3
    gemm2_kernel<<<dim3(4, Bb), 256, G2_SMEM>>>(out_h, W_ho, b_ho, out_x);    // 4
    x0_copy_kernel<<<(Bb * DOUT + 255) / 256, 256>>>(x0, out_x);              // 5
}

// round 14
// speedup vs baseline: 1.0497x; 1.0497x over previous
#include <cuda_runtime.h>
#include <cuda_fp16.h>

// Problem constants
#define Bb    256
#define Tt    512
#define DIN   128
#define Hh    256
#define DOUT  64
#define KTOT  384
#define LEAK  0.01f

// 64MB fp16 scratch: U[b][t][h] = inputs[b][t] @ W_u^T  (k < DIN part)
__device__ __half g_U[(size_t)Bb * Tt * Hh];

// ---- packed fp32x2 helpers (for gemm2) ----
__device__ __forceinline__ void ffma2(unsigned long long& acc,
                                      unsigned long long a, unsigned long long b) {
    asm("fma.rn.f32x2 %0, %1, %2, %0;" : "+l"(acc) : "l"(a), "l"(b));
}
__device__ __forceinline__ float2 unpackf2(unsigned long long v) {
    float2 r;
    asm("mov.b64 {%0, %1}, %2;" : "=f"(r.x), "=f"(r.y) : "l"(v));
    return r;
}
__device__ __forceinline__ float lrelu(float x) {
    return x > 0.f ? x : LEAK * x;
}

// ============================================================================
// Precompute U = inputs @ W_u^T via fp16 mma.
// v4: CTA = 128 m-rows x ALL 256 n-cols, 256 threads (8 warps, reg cap 255).
// inputs read ONCE from DRAM; W staged once (L2-resident across CTAs).
// Warp wi owns m-rows [wi*16, wi*16+16); A-frags hoisted; d[32][4] accums.
// grid = 1024, 102 KB dynamic smem.
// ============================================================================
#define PCPAD 136
#define PC_SMEM ((128 + 256) * PCPAD * 2)   // 104448 bytes

__global__ void __launch_bounds__(256)
u_precompute_kernel(const float* __restrict__ inputs,   // [B*T, DIN]
                    const float* __restrict__ W_ih)     // [H, KTOT]
{
    extern __shared__ __half psm[];
    __half* sA = psm;                  // [128][PCPAD]
    __half* sW = psm + 128 * PCPAD;    // [256][PCPAD]
    const int t  = threadIdx.x;
    const int m0 = (int)blockIdx.x * 128;

    for (int i = t; i < 128 * 32; i += 256) {
        int row = i >> 5, c4 = i & 31;
        float4 v = *(const float4*)(inputs + (size_t)(m0 + row) * DIN + 4 * c4);
        __half2 h01 = __floats2half2_rn(v.x, v.y);
        __half2 h23 = __floats2half2_rn(v.z, v.w);
        *(uint2*)(sA + row * PCPAD + 4 * c4) =
            make_uint2(*(unsigned*)&h01, *(unsigned*)&h23);
    }
    for (int i = t; i < 256 * 32; i += 256) {
        int row = i >> 5, c4 = i & 31;
        float4 v = *(const float4*)(W_ih + (size_t)row * KTOT + 4 * c4);
        __half2 h01 = __floats2half2_rn(v.x, v.y);
        __half2 h23 = __floats2half2_rn(v.z, v.w);
        *(uint2*)(sW + row * PCPAD + 4 * c4) =
            make_uint2(*(unsigned*)&h01, *(unsigned*)&h23);
    }
    __syncthreads();

    const int wi = t >> 5, lane = t & 31;
    const int gg = lane >> 2, tg = lane & 3;
    const int mw = wi * 16;

    // hoist A fragments (reused across all 32 n-frags)
    unsigned af[8][4];
    #pragma unroll
    for (int ki = 0; ki < 8; ki++) {
        int k0 = 16 * ki;
        af[ki][0] = *(const unsigned*)(sA + (mw + gg)     * PCPAD + k0 + 2*tg);
        af[ki][1] = *(const unsigned*)(sA + (mw + 8 + gg) * PCPAD + k0 + 2*tg);
        af[ki][2] = *(const unsigned*)(sA + (mw + gg)     * PCPAD + k0 + 2*tg + 8);
        af[ki][3] = *(const unsigned*)(sA + (mw + 8 + gg) * PCPAD + k0 + 2*tg + 8);
    }

    float d[32][4];
    #pragma unroll
    for (int nf = 0; nf < 32; nf++)
        #pragma unroll
        for (int c = 0; c < 4; c++) d[nf][c] = 0.f;

    #pragma unroll
    for (int ki = 0; ki < 8; ki++) {
        int k0 = 16 * ki;
        #pragma unroll
        for (int nf = 0; nf < 32; nf++) {
            unsigned b0 = *(const unsigned*)(sW + (8*nf + gg) * PCPAD + k0 + 2*tg);
            unsigned b1 = *(const unsigned*)(sW + (8*nf + gg) * PCPAD + k0 + 2*tg + 8);
            asm("mma.sync.aligned.m16n8k16.row.col.f32.f16.f16.f32 "
                "{%0,%1,%2,%3}, {%4,%5,%6,%7}, {%8,%9}, {%0,%1,%2,%3};"
                : "+f"(d[nf][0]), "+f"(d[nf][1]), "+f"(d[nf][2]), "+f"(d[nf][3])
                : "r"(af[ki][0]), "r"(af[ki][1]), "r"(af[ki][2]), "r"(af[ki][3]),
                  "r"(b0), "r"(b1));
        }
    }

    #pragma unroll
    for (int nf = 0; nf < 32; nf++) {
        __half2 lo = __floats2half2_rn(d[nf][0], d[nf][1]);
        __half2 hi = __floats2half2_rn(d[nf][2], d[nf][3]);
        size_t r0 = (size_t)(m0 + mw + gg)     * Hh + 8*nf + 2*tg;
        size_t r1 = (size_t)(m0 + mw + 8 + gg) * Hh + 8*nf + 2*tg;
        *(unsigned*)&g_U[r0] = *(unsigned*)&lo;
        *(unsigned*)&g_U[r1] = *(unsigned*)&hi;
    }
}

// ============================================================================
// Persistent recurrence on TENSOR CORES (exact R12 kernel — 370us validated):
// 128 CTAs x 256 threads, W_hh register-resident B-fragments, 1 BAR/step.
// ============================================================================
#define SH_PAD 264

__global__ void __launch_bounds__(256, 1)
rnn_persist_kernel(const float* __restrict__ h0,       // [B, H]
                   const float* __restrict__ W_ih,     // [H, KTOT]
                   const float* __restrict__ b_ih,     // [H]
                   float* __restrict__ out_h)          // [B, T+1, H]
{
    __shared__ __half shH[2][2][SH_PAD];   // [buf][row][col]

    const int t    = threadIdx.x;
    const int wi   = t >> 5;               // warp: n-cols [wi*32, wi*32+32)
    const int lane = t & 31;
    const bool active = (lane < 8);
    const int r    = (lane >> 2) & 1;
    const int tg   = lane & 3;
    const int row0 = (int)blockIdx.x * 2;

    unsigned bfr[4][16][2];
    #pragma unroll
    for (int nt = 0; nt < 4; nt++) {
        const int n = wi * 32 + nt * 8 + (lane >> 2);
        const float* wr = W_ih + (size_t)n * KTOT + DIN;
        #pragma unroll
        for (int kt = 0; kt < 16; kt++) {
            float2 f0 = __ldg((const float2*)(wr + kt * 16 + 2 * tg));
            float2 f1 = __ldg((const float2*)(wr + kt * 16 + 2 * tg + 8));
            __half2 h0v = __floats2half2_rn(f0.x, f0.y);
            __half2 h1v = __floats2half2_rn(f1.x, f1.y);
            bfr[nt][kt][0] = *(unsigned*)&h0v;
            bfr[nt][kt][1] = *(unsigned*)&h1v;
        }
    }

    for (int i = t; i < 2 * Hh; i += 256) {
        int rr = i >> 8, c = i & 255;
        float v = h0[(size_t)(row0 + rr) * Hh + c];
        shH[0][rr][c] = __float2half_rn(v);
        out_h[(size_t)(row0 + rr) * (Tt + 1) * Hh + c] = v;
    }

    int coff[4];
    float2 bi[4];
    #pragma unroll
    for (int nt = 0; nt < 4; nt++) {
        coff[nt] = wi * 32 + nt * 8 + 2 * tg;
        bi[nt] = active ? __ldg((const float2*)(b_ih + coff[nt]))
                        : make_float2(0.f, 0.f);
    }
    const __half* Ub = g_U + (size_t)(row0 + r) * Tt * Hh;
    float* hx = out_h + (size_t)(row0 + r) * (Tt + 1) * Hh;

    unsigned cU[4] = {0, 0, 0, 0};
    if (active) {
        #pragma unroll
        for (int nt = 0; nt < 4; nt++)
            cU[nt] = *(const unsigned*)(Ub + coff[nt]);
    }

    const unsigned zero = 0;
    __syncthreads();

    #pragma unroll 1
    for (int step = 0; step < Tt; step++) {
        const int p = step & 1;

        unsigned nU[4] = {0, 0, 0, 0};
        if (active && step + 1 < Tt) {
            #pragma unroll
            for (int nt = 0; nt < 4; nt++)
                nU[nt] = *(const unsigned*)(Ub + (size_t)(step + 1) * Hh + coff[nt]);
        }

        float d[4][4];
        #pragma unroll
        for (int nt = 0; nt < 4; nt++)
            #pragma unroll
            for (int c = 0; c < 4; c++) d[nt][c] = 0.f;

        #pragma unroll
        for (int kt = 0; kt < 16; kt++) {
            unsigned a0 = 0, a2 = 0;
            if (active) {
                a0 = *(const unsigned*)&shH[p][r][kt * 16 + 2 * tg];
                a2 = *(const unsigned*)&shH[p][r][kt * 16 + 2 * tg + 8];
            }
            #pragma unroll
            for (int nt = 0; nt < 4; nt++) {
                asm("mma.sync.aligned.m16n8k16.row.col.f32.f16.f16.f32 "
                    "{%0,%1,%2,%3}, {%4,%5,%6,%7}, {%8,%9}, {%0,%1,%2,%3};"
                    : "+f"(d[nt][0]), "+f"(d[nt][1]), "+f"(d[nt][2]), "+f"(d[nt][3])
                    : "r"(a0), "r"(zero), "r"(a2), "r"(zero),
                      "r"(bfr[nt][kt][0]), "r"(bfr[nt][kt][1]));
            }
        }

        if (active) {
            #pragma unroll
            for (int nt = 0; nt < 4; nt++) {
                float2 u = __half22float2(*(const __half2*)&cU[nt]);
                float xv = lrelu(d[nt][0] + u.x + bi[nt].x);
                float yv = lrelu(d[nt][1] + u.y + bi[nt].y);
                __half2 hh = __floats2half2_rn(xv, yv);
                *(unsigned*)&shH[p ^ 1][r][coff[nt]] = *(unsigned*)&hh;
                *(float2*)(hx + (size_t)(step + 1) * Hh + coff[nt]) =
                    make_float2(xv, yv);
            }
        }
        #pragma unroll
        for (int nt = 0; nt < 4; nt++) cU[nt] = nU[nt];

        __syncthreads();
    }
}

// ============================================================================
// Output projection (fp32 FFMA2, validated) + fused x0 row.
// ============================================================================
#define G2_ROWS 32
#define G2_SMEM (64*64*16 + G2_ROWS*Hh*4)   // 98304

__global__ void __launch_bounds__(256, 2)
gemm2_kernel(const float* __restrict__ out_h,
             const float* __restrict__ W_ho,
             const float* __restrict__ b_ho,
             const float* __restrict__ x0,
             float* __restrict__ out_x)
{
    extern __shared__ float smem[];
    float* sw = smem;            // [64 j4][64 d] float4 view
    float* sh = smem + 16384;    // [32 rows][256]

    const int t   = threadIdx.x;
    const int b   = blockIdx.y;
    const int tt0 = 1 + (int)blockIdx.x * 128;

    // fused x0 row (tile 0 only)
    if (blockIdx.x == 0 && t < DOUT)
        out_x[(size_t)b * (Tt + 1) * DOUT + t] = x0[(size_t)b * DOUT + t];

    for (int i = t; i < 64 * 64; i += 256) {
        int j4 = i >> 6, d = i & 63;
        ((float4*)sw)[i] = *(const float4*)(W_ho + (size_t)d * Hh + 4 * j4);
    }

    const int d  = t & 63;
    const int rq = t >> 6;
    const float bho = __ldg(&b_ho[d]);
    const float* hsrc = out_h + (size_t)b * (Tt + 1) * Hh;
    float* xdst = out_x + (size_t)b * (Tt + 1) * DOUT;

    #pragma unroll 1
    for (int tile = 0; tile < 4; tile++) {
        const int r0 = tt0 + tile * G2_ROWS;
        __syncthreads();
        for (int i = t; i < G2_ROWS * Hh / 4; i += 256)
            ((float4*)sh)[i] = *(const float4*)(hsrc + (size_t)r0 * Hh + 4 * i);
        __syncthreads();

        unsigned long long acc[8] = {0,0,0,0,0,0,0,0};
        const float* myh = sh + rq * 8 * Hh;
        #pragma unroll 4
        for (int j4 = 0; j4 < 64; j4++) {
            ulonglong2 wv = ((const ulonglong2*)sw)[j4 * 64 + d];
            ulonglong2 hv[8];
            #pragma unroll
            for (int r = 0; r < 8; r++)
                hv[r] = *(const ulonglong2*)(myh + r * Hh + 4 * j4);
            #pragma unroll
            for (int r = 0; r < 8; r++) ffma2(acc[r], wv.x, hv[r].x);
            #pragma unroll
            for (int r = 0; r < 8; r++) ffma2(acc[r], wv.y, hv[r].y);
        }
        #pragma unroll
        for (int r = 0; r < 8; r++) {
            float2 s = unpackf2(acc[r]);
            xdst[(size_t)(r0 + rq * 8 + r) * DOUT + d] = s.x + s.y + bho;
        }
    }
}

// Keep the persistent kernel at launch index 3 mod 6 (ncu capture slot).
__global__ void nop_a_kernel() {}
__global__ void nop_b_kernel() {}
__global__ void nop_c_kernel() {}

extern "C" void kernel_launch(void* const* d_in, const int* in_sizes, int n_in,
                              void* d_out, int out_size) {
    const float* inputs = (const float*)d_in[0];
    const float* x0     = (const float*)d_in[1];
    const float* h0     = (const float*)d_in[2];
    const float* W_ih   = (const float*)d_in[3];
    const float* b_ih   = (const float*)d_in[4];
    const float* W_ho   = (const float*)d_in[5];
    const float* b_ho   = (const float*)d_in[6];

    float* out_x = (float*)d_out;                                  // [B, T+1, DOUT]
    float* out_h = out_x + (size_t)Bb * (Tt + 1) * DOUT;           // [B, T+1, H]

    cudaFuncSetAttribute(gemm2_kernel,
                         cudaFuncAttributeMaxDynamicSharedMemorySize,
                         (int)G2_SMEM);
    cudaFuncSetAttribute(u_precompute_kernel,
                         cudaFuncAttributeMaxDynamicSharedMemorySize,
                         (int)PC_SMEM);

    u_precompute_kernel<<<Bb * Tt / 128, 256, PC_SMEM>>>(inputs, W_ih);        // 0
    nop_a_kernel<<<1, 32>>>();                                                 // 1
    nop_b_kernel<<<1, 32>>>();                                                 // 2
    rnn_persist_kernel<<<Bb / 2, 256>>>(h0, W_ih, b_ih, out_h);                // 3
    gemm2_kernel<<<dim3(4, Bb), 256, G2_SMEM>>>(out_h, W_ho, b_ho, x0, out_x); // 4
    nop_c_kernel<<<1, 32>>>();                                                 // 5
}